// round 16
// baseline (speedup 1.0000x reference)
#include <cuda_runtime.h>
#include <cuda_bf16.h>

#define DIM  64
#define NVOX (DIM*DIM*DIM)       // 262144
#define NB_LOSS (NVOX/256)       // 1024 blocks for the loss kernel
#define NB_UF 256                // fused UF kernel: 256 blocks x 1024 threads

// Scratch (no device allocation allowed in kernel_launch)
__device__ int   g_parent[2*NVOX];
__device__ int   g_lab2[2*NVOX];    // interleaved: [2i]=vol0 label, [2i+1]=vol1 label
__device__ float g_partial[NB_LOSS];
__device__ unsigned g_count;
__device__ unsigned g_bar[2];       // epoch-based grid barrier counters (monotonic)

// ---------------- grid-wide spin barrier (epoch/ticket based; replay-safe) ----

__device__ __forceinline__ void gbar(int id) {
    __syncthreads();
    if (threadIdx.x == 0) {
        __threadfence();
        unsigned ticket = atomicAdd(&g_bar[id], 1u);
        unsigned target = ticket - (ticket & (NB_UF - 1)) + NB_UF;
        while ((int)(*(volatile unsigned*)&g_bar[id] - target) < 0) { }
        __threadfence();
    }
    __syncthreads();
}

// ---------------- global union-find ----------------

__device__ __forceinline__ int uf_find(int x) {
    int p = g_parent[x];
    while (p != x) {
        int gp = g_parent[p];
        if (gp != p) g_parent[x] = gp;   // path halving; benign race
        x = p;
        p = gp;
    }
    return x;
}

__device__ __forceinline__ void uf_unite(int a, int b) {
    a = uf_find(a);
    b = uf_find(b);
    while (a != b) {
        if (a < b) { int t = a; a = b; b = t; }   // link larger index under smaller
        int old = atomicCAS(&g_parent[a], a, b);
        if (old == a) return;
        a = uf_find(old);
        b = uf_find(b);
    }
}

// ---------------- shared-memory union-find ----------------

__device__ __forceinline__ int sfind(int* sp, int x) {
    int p = sp[x];
    while (p != x) {
        int gp = sp[p];
        if (gp != p) sp[x] = gp;
        x = p;
        p = gp;
    }
    return p;
}

__device__ __forceinline__ void sunite(int* sp, int a, int b) {
    a = sfind(sp, a);
    b = sfind(sp, b);
    while (a != b) {
        if (a < b) { int t = a; a = b; b = t; }
        int old = atomicCAS(&sp[a], a, b);
        if (old == a) return;
        a = sfind(sp, old);
        b = sfind(sp, b);
    }
}

// border-edge index -> (voxel i, stride) ; idx < 180224
__device__ __forceinline__ void border_edge(int idx, int& i, int& stride) {
    int vol = (idx >= 90112);
    int r   = idx - vol * 90112;
    int volOff = vol * NVOX;
    if (r < 28672) {
        int x = r & 63, z = (r >> 6) & 63, ky = r >> 12;
        int y = ky * 8 + 7;
        i = volOff + ((z << 12) | (y << 6) | x);
        stride = 64;
    } else {
        int s = r - 28672;
        int x = s & 63, y = (s >> 6) & 63, kz = s >> 12;
        int z = kz * 4 + 3;
        i = volOff + ((z << 12) | (y << 6) | x);
        stride = 4096;
    }
}

// ---------------- fused UF kernel: CCL + border + flatten (best config) -----
// 256 blocks x 1024 threads, all co-resident (2 blocks/SM x 148 SMs >= 256),
// so the grid-wide spin barriers cannot deadlock.

__global__ void __launch_bounds__(1024, 2)
k_uf(const float* __restrict__ pred, const float* __restrict__ labf) {
    __shared__ int sp[2048];
    int b = blockIdx.x;
    if (b == 0 && threadIdx.x == 0) g_count = 0u;   // reset loss-block counter
    int lane = threadIdx.x & 31;

    // ---- phase 1: per-tile CCL (one 64x8x4 tile per block) ----
    {
        int vol = b >> 7;
        int t   = b & 127;
        int y0  = (t & 7) << 3;
        int z0  = (t >> 3) << 2;
        const float* src = vol ? labf : pred;
        int volOff = vol * NVOX;

        // init: local idx l = lx | ly<<6 | lz<<9. Each warp = 32 consecutive
        // lx (half an x-row). Parent = start of fg run within half-row.
        #pragma unroll
        for (int k = 0; k < 2; k++) {
            int l  = threadIdx.x + 1024 * k;
            int lx = l & 63;
            int g  = ((z0 + (l >> 9)) << 12) | ((y0 + ((l >> 6) & 7)) << 6) | lx;
            bool fg = src[g] > 0.0f;
            unsigned m = __ballot_sync(0xffffffffu, fg);
            int v = -1;
            if (fg) {
                unsigned zeros_below = ~m & ((1u << lane) - 1u);
                int startLane = zeros_below ? (32 - __clz(zeros_below)) : 0;
                v = (l & ~63) | (lx & 32) | startLane;
            }
            sp[l] = v;
        }
        __syncthreads();

        // unions: half-row stitch (lx==32), y edges, z edges (deduped).
        #pragma unroll
        for (int k = 0; k < 2; k++) {
            int l  = threadIdx.x + 1024 * k;
            int lx = l & 63, ly = (l >> 6) & 7, lz = l >> 9;
            int s  = sp[l];
            bool fg = (s >= 0);
            int sy = (ly < 7) ? sp[l + 64]  : -1;
            int sz = (lz < 3) ? sp[l + 512] : -1;
            unsigned my = __ballot_sync(0xffffffffu, fg && sy >= 0);
            unsigned mz = __ballot_sync(0xffffffffu, fg && sz >= 0);
            if (fg) {
                if (lx == 32 && sp[l - 1] >= 0) sunite(sp, s, sp[l - 1]);
                if (sy >= 0 && !(lane && ((my >> (lane - 1)) & 1u))) sunite(sp, s, sy);
                if (sz >= 0 && !(lane && ((mz >> (lane - 1)) & 1u))) sunite(sp, s, sz);
            }
        }
        __syncthreads();

        // flatten local roots -> global indices
        #pragma unroll
        for (int k = 0; k < 2; k++) {
            int l  = threadIdx.x + 1024 * k;
            int g  = ((z0 + (l >> 9)) << 12) | ((y0 + ((l >> 6) & 7)) << 6) | (l & 63);
            int v;
            if (sp[l] < 0) v = -1;
            else {
                int r  = sfind(sp, l);
                int rx = r & 63, ry = (r >> 6) & 7, rz = r >> 9;
                v = volOff + (((z0 + rz) << 12) | ((y0 + ry) << 6) | rx);
            }
            g_parent[volOff + g] = v;
        }
    }

    gbar(0);

    // ---- phase 2: cross-tile border unions (180224 edges, ballot-deduped) ----
    {
        int idx = b * 1024 + threadIdx.x;
        if (idx < 180224) {
            int i, stride;
            border_edge(idx, i, stride);
            bool both = (g_parent[i] >= 0) && (g_parent[i + stride] >= 0);
            unsigned mm = __ballot_sync(__activemask(), both);
            // prev-lane edge (x-1) with both endpoints fg subsumes ours.
            if (both && !(lane && ((mm >> (lane - 1)) & 1u))) uf_unite(i, i + stride);
        }
    }

    gbar(1);

    // ---- phase 3: flatten to interleaved labels (1 voxel x 2 vols / thread) --
    {
        int i  = b * 1024 + threadIdx.x;   // < NVOX
        int p0 = g_parent[i];
        int p1 = g_parent[NVOX + i];
        int r0 = p0, r1 = p1;
        bool d0 = (p0 < 0) || (p0 == i);
        bool d1 = (p1 < 0) || (p1 == NVOX + i);
        while (!(d0 && d1)) {
            int n0, n1;
            if (!d0) n0 = g_parent[r0];
            if (!d1) n1 = g_parent[r1];
            if (!d0) { d0 = (n0 == r0); r0 = n0; }
            if (!d1) { d1 = (n1 == r1); r1 = n1; }
        }
        int2 o;
        o.x = (p0 < 0) ? 0 : (r0 + 1);
        o.y = (p1 < 0) ? 0 : (r1 + 1);
        *reinterpret_cast<int2*>(&g_lab2[2*i]) = o;
    }
}

// ---------------- 27-bit window morphology ----------------
// bit p = dz*9 + dy*3 + dx  (dz,dy,dx in 0..2), matching reference seed layout.

__device__ __forceinline__ unsigned xd(unsigned m) {
    const unsigned X0 = 0x1249249u;
    const unsigned X2 = 0x4924924u;
    return m | ((m & ~X2) << 1) | ((m & ~X0) >> 1);
}
__device__ __forceinline__ unsigned yd(unsigned m) {
    const unsigned Y0 = 0x01C0E07u;
    const unsigned Y2 = 0x70381C0u;
    return m | ((m & ~Y2) << 3) | ((m & ~Y0) >> 3);
}
__device__ __forceinline__ unsigned zd(unsigned m) {
    return (m | (m << 9) | (m >> 9)) & 0x7FFFFFFu;
}
__device__ __forceinline__ unsigned dil26(unsigned m) { return zd(yd(xd(m))); }
__device__ __forceinline__ unsigned dil18(unsigned m) {
    unsigned zm = zd(m);
    return xd(yd(m)) | xd(zm) | yd(zm);
}

// Pick a low-eccentricity seed: prefer face-adjacent bits (6-neighbors of center).
#define FACES 0x415410u
__device__ __forceinline__ unsigned pick_seed(unsigned m) {
    unsigned f = m & FACES;
    unsigned src = f ? f : m;
    return src & (0u - src);
}

// k_loss: block covers 4 x-rows (fixed z, y in {4a..4a+3}). Stage the
// 3(z) x 6(y) x 64(x) label-pair halo in shared; all 27 window loads become
// LDS at compile-time immediate offsets (clamping baked in at staging).
__global__ void k_loss(const float* __restrict__ pred, const float* __restrict__ labf,
                       float* __restrict__ out) {
    __shared__ int2  tile[3][6][64];   // 9216 B
    __shared__ float sdata[256];
    __shared__ bool  isLast;

    int tid = threadIdx.x;
    int i   = blockIdx.x * 256 + tid;
    int x   = i & 63;
    int ly  = (tid >> 6);              // 0..3, y = yb + ly
    int yb  = (i >> 6) & 60;           // block's base y (multiple of 4)
    int z   = i >> 12;                 // fixed per block

    // stage halo: 1152 int2, clamped in y/z
    for (int idx = tid; idx < 1152; idx += 256) {
        int xx  = idx & 63;
        int row = idx >> 6;            // 0..17
        int yy  = row % 6;
        int zz  = row / 6;
        int gy  = min(max(yb + yy - 1, 0), 63);
        int gz  = min(max(z + zz - 1, 0), 63);
        int g   = (gz << 12) | (gy << 6) | xx;
        tile[zz][yy][xx] = *reinterpret_cast<const int2*>(&g_lab2[2*g]);
    }
    __syncthreads();

    int xm1 = max(x - 1, 0);
    int xp1 = min(x + 1, 63);

    int2 cen = tile[1][ly + 1][x];
    int c0 = cen.x, c1 = cen.y;

    unsigned m0 = 0u, m1 = 0u;
    int bit = 0;
    #pragma unroll
    for (int zz = 0; zz < 3; zz++) {
        #pragma unroll
        for (int dy = 0; dy < 3; dy++) {
            int2 l0 = tile[zz][ly + dy][xm1];
            int2 l1 = tile[zz][ly + dy][x];
            int2 l2 = tile[zz][ly + dy][xp1];
            if (l0.x != c0) m0 |= 1u << (bit + 0);
            if (l1.x != c0) m0 |= 1u << (bit + 1);
            if (l2.x != c0) m0 |= 1u << (bit + 2);
            if (l0.y != c1) m1 |= 1u << (bit + 0);
            if (l1.y != c1) m1 |= 1u << (bit + 1);
            if (l2.y != c1) m1 |= 1u << (bit + 2);
            bit += 3;
        }
    }

    const unsigned ALL = 0x7FFFFFFu;
    const unsigned CEN = 1u << 13;
    unsigned a  = c0 ? m0 : 0u;                      // 18-conn target
    unsigned bm = c0 ? ((~m0 & ALL) & ~CEN) : 0u;    // 26-conn target
    unsigned c  = c1 ? m1 : 0u;
    unsigned d  = c1 ? ((~m1 & ALL) & ~CEN) : 0u;

    unsigned s0 = pick_seed(a);
    unsigned s1 = pick_seed(bm);
    unsigned s2 = pick_seed(c);
    unsigned s3 = pick_seed(d);

    // Peel 3 vote-free iterations, then vote loop.
    #pragma unroll
    for (int it = 0; it < 3; it++) {
        s0 = dil18(s0) & a;
        s1 = dil26(s1) & bm;
        s2 = dil18(s2) & c;
        s3 = dil26(s3) & d;
    }
    bool changed = true;
    while (__any_sync(0xffffffffu, changed)) {
        unsigned t0 = dil18(s0) & a;
        unsigned t1 = dil26(s1) & bm;
        unsigned t2 = dil18(s2) & c;
        unsigned t3 = dil26(s3) & d;
        changed = ((t0 ^ s0) | (t1 ^ s1) | (t2 ^ s2) | (t3 ^ s3)) != 0u;
        s0 = t0; s1 = t1; s2 = t2; s3 = t3;
    }
    bool one0 = (s0 == a)  && (a  != 0u);
    bool one1 = (s1 == bm) && (bm != 0u);
    bool one2 = (s2 == c)  && (c  != 0u);
    bool one3 = (s3 == d)  && (d  != 0u);
    bool ns0 = (c0 != 0) && !(one0 && one1);
    bool ns1 = (c1 != 0) && !(one2 && one3);

    float p = pred[i];
    float l = labf[i];
    float cost = fmaxf(p, 0.0f) - p * l + __logf(1.0f + __expf(-fabsf(p)));
    float w = (ns0 || ns1) ? 5.0f : 1.0f;

    sdata[tid] = w * cost;
    __syncthreads();
    #pragma unroll
    for (int s = 128; s > 0; s >>= 1) {
        if (tid < s) sdata[tid] += sdata[tid + s];
        __syncthreads();
    }
    if (tid == 0) {
        g_partial[blockIdx.x] = sdata[0];
        __threadfence();
        unsigned old = atomicAdd(&g_count, 1u);
        isLast = (old == (unsigned)(gridDim.x - 1));
    }
    __syncthreads();

    if (isLast) {
        float v = 0.0f;
        for (int j = tid; j < NB_LOSS; j += 256) v += g_partial[j];
        sdata[tid] = v;
        __syncthreads();
        #pragma unroll
        for (int s = 128; s > 0; s >>= 1) {
            if (tid < s) sdata[tid] += sdata[tid + s];
            __syncthreads();
        }
        if (tid == 0) out[0] = sdata[0] / (float)NVOX;
    }
}

extern "C" void kernel_launch(void* const* d_in, const int* in_sizes, int n_in,
                              void* d_out, int out_size) {
    (void)in_sizes; (void)n_in; (void)out_size;
    const float* pred = (const float*)d_in[0];
    const float* labf = (const float*)d_in[1];
    float* out = (float*)d_out;

    k_uf<<<NB_UF, 1024>>>(pred, labf);
    k_loss<<<NB_LOSS, 256>>>(pred, labf, out);
}

// round 17
// speedup vs baseline: 1.0615x; 1.0615x over previous
#include <cuda_runtime.h>
#include <cuda_bf16.h>

#define DIM  64
#define NVOX (DIM*DIM*DIM)       // 262144
#define NB_LOSS (NVOX/256)       // 1024 blocks for the loss kernel
#define NB_UF 256                // fused UF kernel: 256 blocks x 1024 threads

// Scratch (no device allocation allowed in kernel_launch)
__device__ int   g_parent[2*NVOX];
__device__ int   g_lab2[2*NVOX];    // interleaved: [2i]=vol0 label, [2i+1]=vol1 label
__device__ float g_partial[NB_LOSS];
__device__ unsigned g_count;
__device__ unsigned g_bar[2];       // epoch-based grid barrier counters (monotonic)

// ---------------- grid-wide spin barrier (epoch/ticket based; replay-safe) ----

__device__ __forceinline__ void gbar(int id) {
    __syncthreads();
    if (threadIdx.x == 0) {
        __threadfence();
        unsigned ticket = atomicAdd(&g_bar[id], 1u);
        unsigned target = ticket - (ticket & (NB_UF - 1)) + NB_UF;
        while ((int)(*(volatile unsigned*)&g_bar[id] - target) < 0) { }
        __threadfence();
    }
    __syncthreads();
}

// ---------------- global union-find ----------------

__device__ __forceinline__ int uf_find(int x) {
    int p = g_parent[x];
    while (p != x) {
        int gp = g_parent[p];
        if (gp != p) g_parent[x] = gp;   // path halving; benign race
        x = p;
        p = gp;
    }
    return x;
}

__device__ __forceinline__ void uf_unite(int a, int b) {
    a = uf_find(a);
    b = uf_find(b);
    while (a != b) {
        if (a < b) { int t = a; a = b; b = t; }   // link larger index under smaller
        int old = atomicCAS(&g_parent[a], a, b);
        if (old == a) return;
        a = uf_find(old);
        b = uf_find(b);
    }
}

// ---------------- shared-memory union-find ----------------

__device__ __forceinline__ int sfind(int* sp, int x) {
    int p = sp[x];
    while (p != x) {
        int gp = sp[p];
        if (gp != p) sp[x] = gp;
        x = p;
        p = gp;
    }
    return p;
}

__device__ __forceinline__ void sunite(int* sp, int a, int b) {
    a = sfind(sp, a);
    b = sfind(sp, b);
    while (a != b) {
        if (a < b) { int t = a; a = b; b = t; }
        int old = atomicCAS(&sp[a], a, b);
        if (old == a) return;
        a = sfind(sp, old);
        b = sfind(sp, b);
    }
}

// border-edge index -> (voxel i, stride) ; idx < 180224
__device__ __forceinline__ void border_edge(int idx, int& i, int& stride) {
    int vol = (idx >= 90112);
    int r   = idx - vol * 90112;
    int volOff = vol * NVOX;
    if (r < 28672) {
        int x = r & 63, z = (r >> 6) & 63, ky = r >> 12;
        int y = ky * 8 + 7;
        i = volOff + ((z << 12) | (y << 6) | x);
        stride = 64;
    } else {
        int s = r - 28672;
        int x = s & 63, y = (s >> 6) & 63, kz = s >> 12;
        int z = kz * 4 + 3;
        i = volOff + ((z << 12) | (y << 6) | x);
        stride = 4096;
    }
}

// ---------------- fused UF kernel: CCL + border + flatten (best config) -----
// 256 blocks x 1024 threads, all co-resident (2 blocks/SM x 148 SMs >= 256),
// so the grid-wide spin barriers cannot deadlock.

__global__ void __launch_bounds__(1024, 2)
k_uf(const float* __restrict__ pred, const float* __restrict__ labf) {
    __shared__ int sp[2048];
    int b = blockIdx.x;
    if (b == 0 && threadIdx.x == 0) g_count = 0u;   // reset loss-block counter
    int lane = threadIdx.x & 31;

    // ---- phase 1: per-tile CCL (one 64x8x4 tile per block) ----
    {
        int vol = b >> 7;
        int t   = b & 127;
        int y0  = (t & 7) << 3;
        int z0  = (t >> 3) << 2;
        const float* src = vol ? labf : pred;
        int volOff = vol * NVOX;

        // init: local idx l = lx | ly<<6 | lz<<9. Each warp = 32 consecutive
        // lx (half an x-row). Parent = start of fg run within half-row.
        #pragma unroll
        for (int k = 0; k < 2; k++) {
            int l  = threadIdx.x + 1024 * k;
            int lx = l & 63;
            int g  = ((z0 + (l >> 9)) << 12) | ((y0 + ((l >> 6) & 7)) << 6) | lx;
            bool fg = src[g] > 0.0f;
            unsigned m = __ballot_sync(0xffffffffu, fg);
            int v = -1;
            if (fg) {
                unsigned zeros_below = ~m & ((1u << lane) - 1u);
                int startLane = zeros_below ? (32 - __clz(zeros_below)) : 0;
                v = (l & ~63) | (lx & 32) | startLane;
            }
            sp[l] = v;
        }
        __syncthreads();

        // unions: half-row stitch (lx==32), y edges, z edges (deduped).
        #pragma unroll
        for (int k = 0; k < 2; k++) {
            int l  = threadIdx.x + 1024 * k;
            int lx = l & 63, ly = (l >> 6) & 7, lz = l >> 9;
            int s  = sp[l];
            bool fg = (s >= 0);
            int sy = (ly < 7) ? sp[l + 64]  : -1;
            int sz = (lz < 3) ? sp[l + 512] : -1;
            unsigned my = __ballot_sync(0xffffffffu, fg && sy >= 0);
            unsigned mz = __ballot_sync(0xffffffffu, fg && sz >= 0);
            if (fg) {
                if (lx == 32 && sp[l - 1] >= 0) sunite(sp, s, sp[l - 1]);
                if (sy >= 0 && !(lane && ((my >> (lane - 1)) & 1u))) sunite(sp, s, sy);
                if (sz >= 0 && !(lane && ((mz >> (lane - 1)) & 1u))) sunite(sp, s, sz);
            }
        }
        __syncthreads();

        // flatten local roots -> global indices
        #pragma unroll
        for (int k = 0; k < 2; k++) {
            int l  = threadIdx.x + 1024 * k;
            int g  = ((z0 + (l >> 9)) << 12) | ((y0 + ((l >> 6) & 7)) << 6) | (l & 63);
            int v;
            if (sp[l] < 0) v = -1;
            else {
                int r  = sfind(sp, l);
                int rx = r & 63, ry = (r >> 6) & 7, rz = r >> 9;
                v = volOff + (((z0 + rz) << 12) | ((y0 + ry) << 6) | rx);
            }
            g_parent[volOff + g] = v;
        }
    }

    gbar(0);

    // ---- phase 2: cross-tile border unions (180224 edges, ballot-deduped) ----
    {
        int idx = b * 1024 + threadIdx.x;
        if (idx < 180224) {
            int i, stride;
            border_edge(idx, i, stride);
            bool both = (g_parent[i] >= 0) && (g_parent[i + stride] >= 0);
            unsigned mm = __ballot_sync(__activemask(), both);
            // prev-lane edge (x-1) with both endpoints fg subsumes ours.
            if (both && !(lane && ((mm >> (lane - 1)) & 1u))) uf_unite(i, i + stride);
        }
    }

    gbar(1);

    // ---- phase 3: flatten to interleaved labels (1 voxel x 2 vols / thread) --
    {
        int i  = b * 1024 + threadIdx.x;   // < NVOX
        int p0 = g_parent[i];
        int p1 = g_parent[NVOX + i];
        int r0 = p0, r1 = p1;
        bool d0 = (p0 < 0) || (p0 == i);
        bool d1 = (p1 < 0) || (p1 == NVOX + i);
        while (!(d0 && d1)) {
            int n0, n1;
            if (!d0) n0 = g_parent[r0];
            if (!d1) n1 = g_parent[r1];
            if (!d0) { d0 = (n0 == r0); r0 = n0; }
            if (!d1) { d1 = (n1 == r1); r1 = n1; }
        }
        int2 o;
        o.x = (p0 < 0) ? 0 : (r0 + 1);
        o.y = (p1 < 0) ? 0 : (r1 + 1);
        *reinterpret_cast<int2*>(&g_lab2[2*i]) = o;
    }
}

// ---------------- 27-bit window morphology ----------------
// bit p = dz*9 + dy*3 + dx  (dz,dy,dx in 0..2), matching reference seed layout.

__device__ __forceinline__ unsigned xd(unsigned m) {
    const unsigned X0 = 0x1249249u;
    const unsigned X2 = 0x4924924u;
    return m | ((m & ~X2) << 1) | ((m & ~X0) >> 1);
}
__device__ __forceinline__ unsigned yd(unsigned m) {
    const unsigned Y0 = 0x01C0E07u;
    const unsigned Y2 = 0x70381C0u;
    return m | ((m & ~Y2) << 3) | ((m & ~Y0) >> 3);
}
__device__ __forceinline__ unsigned zd(unsigned m) {
    return (m | (m << 9) | (m >> 9)) & 0x7FFFFFFu;
}
__device__ __forceinline__ unsigned dil26(unsigned m) { return zd(yd(xd(m))); }
// Factored: xd(yd(m)) | xd(zd(m)) | yd(zd(m)) == xd(yd(m)|zd(m)) | yd(zd(m))
__device__ __forceinline__ unsigned dil18(unsigned m) {
    unsigned ym = yd(m), zm = zd(m);
    return xd(ym | zm) | yd(zm);
}

// Pick a low-eccentricity seed: prefer face-adjacent bits (6-neighbors of center).
#define FACES 0x415410u
__device__ __forceinline__ unsigned pick_seed(unsigned m) {
    unsigned f = m & FACES;
    unsigned src = f ? f : m;
    return src & (0u - src);
}

__global__ void k_loss(const float* __restrict__ pred, const float* __restrict__ labf,
                       float* __restrict__ out) {
    __shared__ float swarp[8];
    __shared__ float sdata[256];
    __shared__ bool  isLast;
    int tid = threadIdx.x;
    int i = blockIdx.x * 256 + tid;

    int x = i & 63, y = (i >> 6) & 63, z = i >> 12;

    int2 cc = *reinterpret_cast<const int2*>(&g_lab2[2*i]);
    int c0 = cc.x, c1 = cc.y;

    unsigned m0 = 0u, m1 = 0u;

    // Warp-uniform interior test: a warp spans 32 consecutive x with fixed
    // (y,z), so this branch does not diverge.
    bool interiorYZ = (unsigned)(y - 1) < 62u && (unsigned)(z - 1) < 62u;

    if (interiorYZ) {
        // Fast path (~94% of warps): 3 clamped base pointers, all 27 loads
        // at compile-time immediate offsets — no per-load address math.
        int xm1 = max(x - 1, 0);
        int xp1 = min(x + 1, 63);
        const int2* pm1 = reinterpret_cast<const int2*>(&g_lab2[2*(i + xm1 - x)]);
        const int2* p0  = reinterpret_cast<const int2*>(&g_lab2[2*i]);
        const int2* pp1 = reinterpret_cast<const int2*>(&g_lab2[2*(i + xp1 - x)]);
        int bit = 0;
        #pragma unroll
        for (int dz = -1; dz <= 1; dz++) {
            #pragma unroll
            for (int dy = -1; dy <= 1; dy++) {
                const int off = dz * 4096 + dy * 64;   // compile-time constant
                int2 l0 = pm1[off];
                int2 l1 = p0[off];
                int2 l2 = pp1[off];
                if (l0.x != c0) m0 |= 1u << (bit + 0);
                if (l1.x != c0) m0 |= 1u << (bit + 1);
                if (l2.x != c0) m0 |= 1u << (bit + 2);
                if (l0.y != c1) m1 |= 1u << (bit + 0);
                if (l1.y != c1) m1 |= 1u << (bit + 1);
                if (l2.y != c1) m1 |= 1u << (bit + 2);
                bit += 3;
            }
        }
    } else {
        // Generic clamped path (y/z boundary warps).
        int bit = 0;
        #pragma unroll
        for (int dz = -1; dz <= 1; dz++) {
            int zz = min(max(z + dz, 0), 63);
            #pragma unroll
            for (int dy = -1; dy <= 1; dy++) {
                int yy = min(max(y + dy, 0), 63);
                int base = (zz << 12) | (yy << 6);
                #pragma unroll
                for (int dx = -1; dx <= 1; dx++) {
                    int xx = min(max(x + dx, 0), 63);
                    int j = base | xx;
                    int2 lb = *reinterpret_cast<const int2*>(&g_lab2[2*j]);
                    if (lb.x != c0) m0 |= (1u << bit);
                    if (lb.y != c1) m1 |= (1u << bit);
                    bit++;
                }
            }
        }
    }

    const unsigned ALL = 0x7FFFFFFu;
    const unsigned CEN = 1u << 13;
    unsigned a  = c0 ? m0 : 0u;                      // 18-conn target
    unsigned bm = c0 ? ((~m0 & ALL) & ~CEN) : 0u;    // 26-conn target
    unsigned c  = c1 ? m1 : 0u;
    unsigned d  = c1 ? ((~m1 & ALL) & ~CEN) : 0u;

    unsigned s0 = pick_seed(a);
    unsigned s1 = pick_seed(bm);
    unsigned s2 = pick_seed(c);
    unsigned s3 = pick_seed(d);

    // Peel 3 vote-free iterations, then vote loop.
    #pragma unroll
    for (int it = 0; it < 3; it++) {
        s0 = dil18(s0) & a;
        s1 = dil26(s1) & bm;
        s2 = dil18(s2) & c;
        s3 = dil26(s3) & d;
    }
    bool changed = true;
    while (__any_sync(0xffffffffu, changed)) {
        unsigned t0 = dil18(s0) & a;
        unsigned t1 = dil26(s1) & bm;
        unsigned t2 = dil18(s2) & c;
        unsigned t3 = dil26(s3) & d;
        changed = ((t0 ^ s0) | (t1 ^ s1) | (t2 ^ s2) | (t3 ^ s3)) != 0u;
        s0 = t0; s1 = t1; s2 = t2; s3 = t3;
    }
    bool one0 = (s0 == a)  && (a  != 0u);
    bool one1 = (s1 == bm) && (bm != 0u);
    bool one2 = (s2 == c)  && (c  != 0u);
    bool one3 = (s3 == d)  && (d  != 0u);
    bool ns0 = (c0 != 0) && !(one0 && one1);
    bool ns1 = (c1 != 0) && !(one2 && one3);

    float p = pred[i];
    float l = labf[i];
    float cost = fmaxf(p, 0.0f) - p * l + __logf(1.0f + __expf(-fabsf(p)));
    float w = (ns0 || ns1) ? 5.0f : 1.0f;
    float v = w * cost;

    // warp shuffle reduction (fixed order, deterministic)
    #pragma unroll
    for (int off = 16; off > 0; off >>= 1)
        v += __shfl_down_sync(0xffffffffu, v, off);
    if ((tid & 31) == 0) swarp[tid >> 5] = v;
    __syncthreads();
    if (tid == 0) {
        float bs = swarp[0] + swarp[1] + swarp[2] + swarp[3]
                 + swarp[4] + swarp[5] + swarp[6] + swarp[7];
        g_partial[blockIdx.x] = bs;
        __threadfence();
        unsigned old = atomicAdd(&g_count, 1u);
        isLast = (old == (unsigned)(gridDim.x - 1));
    }
    __syncthreads();

    if (isLast) {
        float vv = 0.0f;
        for (int j = tid; j < NB_LOSS; j += 256) vv += g_partial[j];
        sdata[tid] = vv;
        __syncthreads();
        #pragma unroll
        for (int s = 128; s > 0; s >>= 1) {
            if (tid < s) sdata[tid] += sdata[tid + s];
            __syncthreads();
        }
        if (tid == 0) out[0] = sdata[0] / (float)NVOX;
    }
}

extern "C" void kernel_launch(void* const* d_in, const int* in_sizes, int n_in,
                              void* d_out, int out_size) {
    (void)in_sizes; (void)n_in; (void)out_size;
    const float* pred = (const float*)d_in[0];
    const float* labf = (const float*)d_in[1];
    float* out = (float*)d_out;

    k_uf<<<NB_UF, 1024>>>(pred, labf);
    k_loss<<<NB_LOSS, 256>>>(pred, labf, out);
}